// round 6
// baseline (speedup 1.0000x reference)
#include <cuda_runtime.h>
#include <cstdint>

#define N_BATCH 256
#define C_DIM   2048
#define C_HALF  1024                 // channels per CTA (2 CTAs per batch)
#define HW      49
#define CH      64                   // c-rows per staged chunk
#define NCHUNK  (C_HALF / CH)        // 16
#define ELEMS   (CH * HW)            // 3136 floats per chunk
#define CHUNK_BYTES (ELEMS * 4)      // 12544 B
#define NBUF    3
// smem: mbar pad (32 floats) + wpack (float4[C_HALF] = 4096 floats) + NBUF x-buffers
#define SMEM_MBAR_FLOATS 32
#define SMEM_FLOATS (SMEM_MBAR_FLOATS + 4 * C_HALF + NBUF * ELEMS)
#define SMEM_BYTES  (SMEM_FLOATS * 4)   // 128 + 16384 + 37632 = 54144 B -> 4 CTAs/SM

// Cross-CTA scratch: partials per (half, n); counter parity makes this
// replay-safe without any zeroing (each launch adds exactly 2 per n).
__device__ float        g_part[2][N_BATCH][5][HW];
__device__ unsigned int g_count[N_BATCH];

__device__ __forceinline__ uint32_t smem_u32(const void* p) {
    return (uint32_t)__cvta_generic_to_shared(p);
}
__device__ __forceinline__ void mbar_init(uint32_t mbar, uint32_t count) {
    asm volatile("mbarrier.init.shared::cta.b64 [%0], %1;" :: "r"(mbar), "r"(count) : "memory");
}
__device__ __forceinline__ void mbar_expect_tx(uint32_t mbar, uint32_t bytes) {
    asm volatile("mbarrier.arrive.expect_tx.shared::cta.b64 _, [%0], %1;"
                 :: "r"(mbar), "r"(bytes) : "memory");
}
__device__ __forceinline__ void bulk_g2s(uint32_t smem_dst, const void* gsrc,
                                         uint32_t bytes, uint32_t mbar) {
    asm volatile("cp.async.bulk.shared::cta.global.mbarrier::complete_tx::bytes "
                 "[%0], [%1], %2, [%3];"
                 :: "r"(smem_dst), "l"(gsrc), "r"(bytes), "r"(mbar) : "memory");
}
__device__ __forceinline__ void mbar_wait(uint32_t mbar, uint32_t parity) {
    uint32_t done;
    asm volatile(
        "{\n\t.reg .pred p;\n\t"
        "mbarrier.try_wait.parity.acquire.cta.shared::cta.b64 p, [%1], %2;\n\t"
        "selp.b32 %0, 1, 0, p;\n\t}"
        : "=r"(done) : "r"(mbar), "r"(parity) : "memory");
    if (!done) {
        asm volatile(
            "{\n\t.reg .pred P1;\n\t"
            "WAIT_LOOP_%=:\n\t"
            "mbarrier.try_wait.parity.acquire.cta.shared::cta.b64 P1, [%0], %1, 0x989680;\n\t"
            "@P1 bra.uni WAIT_DONE_%=;\n\t"
            "bra.uni WAIT_LOOP_%=;\n\t"
            "WAIT_DONE_%=:\n\t}"
            :: "r"(mbar), "r"(parity) : "memory");
    }
}

// Packed f32x2 helpers
__device__ __forceinline__ void pack_dup(uint64_t& dst, float v) {
    asm("mov.b64 %0, {%1, %1};" : "=l"(dst) : "r"(__float_as_uint(v)));
}
__device__ __forceinline__ void fma2(uint64_t& acc, uint64_t xx, uint64_t ww) {
    asm("fma.rn.f32x2 %0, %1, %2, %0;" : "+l"(acc) : "l"(xx), "l"(ww));
}

// Two CTAs per batch n (each owns half of C). Partials combined via scratch +
// atomic counter; second-arriving CTA runs the fused epilogue.
__global__ void __launch_bounds__(256, 4)
rcp_split_kernel(const float* __restrict__ x, const float* __restrict__ mask,
                 const float* __restrict__ W, const float* __restrict__ bvec,
                 float* __restrict__ out) {
    const int n    = blockIdx.x >> 1;
    const int half = blockIdx.x & 1;
    const int tid  = threadIdx.x;
    const int wid  = tid >> 5;
    const int lane = tid & 31;

    extern __shared__ float smem[];
    uint64_t* mbar_s = reinterpret_cast<uint64_t*>(smem);                  // [NBUF]
    float4*   wpack  = reinterpret_cast<float4*>(smem + SMEM_MBAR_FLOATS); // [C_HALF]
    float*    xs     = smem + SMEM_MBAR_FLOATS + 4 * C_HALF;               // NBUF x ELEMS
    __shared__ int w_flag;

    const uint32_t mbar0 = smem_u32(&mbar_s[0]);

    if (tid == 0) {
        #pragma unroll
        for (int b = 0; b < NBUF; b++) mbar_init(mbar0 + 8 * b, 1);
    }

    // Stage this half's W packed: {A0w, A1w, D0w, D1w} per c.
    const int wbase = half * C_HALF;
    for (int c = tid; c < C_HALF; c += 256) {
        int cg = wbase + c;
        wpack[c] = make_float4(W[cg], W[4096 + cg], W[2048 + cg], W[6144 + cg]);
    }

    const float* xn = x + (size_t)n * (C_DIM * HW) + (size_t)half * (C_HALF * HW);

    __syncthreads();   // mbarrier init visible before first bulk issue

    if (tid == 0) {
        #pragma unroll
        for (int pc = 0; pc < NBUF; pc++) {
            uint32_t mb = mbar0 + 8 * pc;
            mbar_expect_tx(mb, CHUNK_BYTES);
            bulk_g2s(smem_u32(xs + pc * ELEMS), xn + pc * ELEMS, CHUNK_BYTES, mb);
        }
    }

    float    s[7]    = {0,0,0,0,0,0,0};
    uint64_t accA[7] = {0,0,0,0,0,0,0};   // packed (a0, a1)
    uint64_t accD[7] = {0,0,0,0,0,0,0};   // packed (d0, d1)

    int buf = 0, phase = 0;
    for (int chunk = 0; chunk < NCHUNK; chunk++) {
        mbar_wait(mbar0 + 8 * buf, phase);

        const float*      xb  = xs + buf * ELEMS;
        const ulonglong2* wp2 = reinterpret_cast<const ulonglong2*>(wpack + chunk * CH);

        #pragma unroll
        for (int it = 0; it < 2; it++) {
            const int cl = lane + 32 * it;
            ulonglong2 w2 = wp2[cl];            // LDS.128: {A0w,A1w},{D0w,D1w}
            const float* row = xb + cl * HW;

            float xv[6];
            #pragma unroll
            for (int i = 0; i < 6; i++) xv[i] = row[wid + 8 * i];  // p<=47 in-bounds

            #pragma unroll
            for (int i = 0; i < 6; i++) {
                uint64_t xx; pack_dup(xx, xv[i]);
                s[i] += xv[i];
                fma2(accA[i], xx, w2.x);
                fma2(accD[i], xx, w2.y);
            }
            if (wid == 0) {                     // i=6 -> p=48 only for wid 0
                float x6 = row[48];
                uint64_t xx; pack_dup(xx, x6);
                s[6] += x6;
                fma2(accA[6], xx, w2.x);
                fma2(accD[6], xx, w2.y);
            }
        }

        __syncthreads();   // everyone done reading this buffer

        if (tid == 0 && chunk + NBUF < NCHUNK) {
            uint32_t mb = mbar0 + 8 * buf;
            mbar_expect_tx(mb, CHUNK_BYTES);
            bulk_g2s(smem_u32(xs + buf * ELEMS), xn + (chunk + NBUF) * ELEMS,
                     CHUNK_BYTES, mb);
        }

        if (++buf == NBUF) { buf = 0; phase ^= 1; }
    }

    // Warp reduce; lane 0 writes partials straight to global scratch.
    float* gp = &g_part[half][n][0][0];
    #pragma unroll
    for (int i = 0; i < 7; i++) {
        int p = wid + 8 * i;
        float vs = s[i];
        float u0 = __uint_as_float((uint32_t)(accA[i] & 0xFFFFFFFFu));
        float u1 = __uint_as_float((uint32_t)(accA[i] >> 32));
        float v0 = __uint_as_float((uint32_t)(accD[i] & 0xFFFFFFFFu));
        float v1 = __uint_as_float((uint32_t)(accD[i] >> 32));
        #pragma unroll
        for (int off = 16; off; off >>= 1) {
            vs += __shfl_xor_sync(0xFFFFFFFFu, vs, off);
            u0 += __shfl_xor_sync(0xFFFFFFFFu, u0, off);
            u1 += __shfl_xor_sync(0xFFFFFFFFu, u1, off);
            v0 += __shfl_xor_sync(0xFFFFFFFFu, v0, off);
            v1 += __shfl_xor_sync(0xFFFFFFFFu, v1, off);
        }
        if (lane == 0 && p < HW) {
            gp[0 * HW + p] = vs;
            gp[1 * HW + p] = u0;
            gp[2 * HW + p] = u1;
            gp[3 * HW + p] = v0;
            gp[4 * HW + p] = v1;
        }
    }
    __syncthreads();   // orders the global partial stores within this CTA

    if (tid == 0) {
        __threadfence();                             // publish partials
        unsigned old = atomicAdd(&g_count[n], 1u);   // monotonic: parity = arrival order
        w_flag = (int)(old & 1u);                    // second arrival wins
    }
    __syncthreads();

    // ---- Fused epilogue: winning CTA, warp 0 only ----
    if (w_flag && wid == 0) {
        __threadfence();   // acquire partner's partials
        const float* p0 = &g_part[0][n][0][0];
        const float* p1 = &g_part[1][n][0][0];
        const float* m  = mask + n * HW;

        // threshold = mean(mask)
        float m0 = m[lane];
        float m1 = (lane + 32 < HW) ? m[lane + 32] : 0.0f;
        float msum = m0 + m1;
        #pragma unroll
        for (int off = 16; off; off >>= 1) msum += __shfl_xor_sync(0xFFFFFFFFu, msum, off);
        const float thr = msum * (1.0f / 49.0f);

        // masked mean + argmax (first-index tie-break, matching jnp.argmax)
        float s_l = p0[lane] + p1[lane];             // k=0 row
        float v0 = (m0 > thr) ? s_l * (1.0f / (float)C_DIM) : 0.0f;
        float bv = v0;
        int   bi = lane;
        if (lane + 32 < HW) {
            float s_h = p0[lane + 32] + p1[lane + 32];
            float v1 = (m1 > thr) ? s_h * (1.0f / (float)C_DIM) : 0.0f;
            if (v1 > bv) { bv = v1; bi = lane + 32; }
        }
        #pragma unroll
        for (int off = 16; off; off >>= 1) {
            float ov = __shfl_xor_sync(0xFFFFFFFFu, bv, off);
            int   oi = __shfl_xor_sync(0xFFFFFFFFu, bi, off);
            if (ov > bv || (ov == bv && oi < bi)) { bv = ov; bi = oi; }
        }
        const int pstar = bi;

        const float A0s = p0[1 * HW + pstar] + p1[1 * HW + pstar];
        const float A1s = p0[2 * HW + pstar] + p1[2 * HW + pstar];
        const float b0 = bvec[0], b1 = bvec[1];
        const float ai = (float)(pstar / 7);
        const float aj = (float)(pstar % 7);
        const float inv_pi = 0.318309886183790672f;

        float dist[2], gap[2];
        float gsum = 0.0f;
        #pragma unroll
        for (int t = 0; t < 2; t++) {
            int p = lane + 32 * t;
            if (p < HW) {
                float D0p = p0[3 * HW + p] + p1[3 * HW + p];
                float D1p = p0[4 * HW + p] + p1[4 * HW + p];
                float pd = fmaxf(A0s + D0p + b0, 0.0f);
                float pa = fmaxf(A1s + D1p + b1, 0.0f);
                if (p == pstar) { pd = 0.0f; pa = 0.0f; }
                float ri = ((float)(p / 7) - ai) * (1.0f / 7.0f);
                float rj = ((float)(p % 7) - aj) * (1.0f / 7.0f);
                float rd = sqrtf(ri * ri + rj * rj);
                float ra = (atan2f(rj, ri) * inv_pi + 1.0f) * 0.5f;
                float g  = pa - ra;
                if (g < 0.0f) g += 1.0f;
                float dl = pd - rd;
                dist[t] = dl * dl;
                gap[t]  = g;
                gsum   += g;
            } else {
                dist[t] = 0.0f; gap[t] = 0.0f;
            }
        }
        #pragma unroll
        for (int off = 16; off; off >>= 1) gsum += __shfl_xor_sync(0xFFFFFFFFu, gsum, off);
        const float gmean = gsum * (1.0f / 49.0f);

        #pragma unroll
        for (int t = 0; t < 2; t++) {
            int p = lane + 32 * t;
            if (p < HW) {
                float gg = gap[t] - gmean;
                out[n * HW + p] = dist[t] + gg * gg;
            }
        }
    }
}

extern "C" void kernel_launch(void* const* d_in, const int* in_sizes, int n_in,
                              void* d_out, int out_size) {
    const float* x    = (const float*)d_in[0];   // (256, 2048, 7, 7)
    const float* mask = (const float*)d_in[1];   // (256, 7, 7)
    const float* W    = (const float*)d_in[2];   // (2, 4096)
    const float* b    = (const float*)d_in[3];   // (2,)
    float* out = (float*)d_out;                  // (256, 7, 7)

    cudaFuncSetAttribute(rcp_split_kernel,
                         cudaFuncAttributeMaxDynamicSharedMemorySize, SMEM_BYTES);

    rcp_split_kernel<<<2 * N_BATCH, 256, SMEM_BYTES>>>(x, mask, W, b, out);
}